// round 3
// baseline (speedup 1.0000x reference)
#include <cuda_runtime.h>
#include <cuda_fp16.h>
#include <cstdint>

// ----------------------------------------------------------------------------
// Problem sizes (fixed by the dataset)
//   x:      [2, 4096, 4096] f32  -> M = 8192 tokens, K = 4096
//   weight: [16384, 4096]   f32  -> N = 16384
//   out:    [2, 4096, 16384] f32
// ----------------------------------------------------------------------------
constexpr int M_DIM = 8192;
constexpr int N_DIM = 16384;
constexpr int K_DIM = 4096;

// GEMM tiling (mma.sync path — tcgen05 is unavailable: harness targets compute_103)
constexpr int BM = 256;
constexpr int BN = 128;
constexpr int BK = 64;               // 64 fp16 = 128 B = one SW128 row
constexpr int KT = K_DIM / BK;       // 64 k-tiles
constexpr int STAGES = 3;

constexpr int A_TILE = BM * BK * 2;              // 32768 B
constexpr int B_TILE = BN * BK * 2;              // 16384 B
constexpr int STAGE_BYTES = A_TILE + B_TILE;     // 49152 B
constexpr int SMEM_BYTES = STAGES * STAGE_BYTES; // 147456 B

// ----------------------------------------------------------------------------
// Scratch (static device memory -- no allocations allowed)
// ----------------------------------------------------------------------------
__device__ __align__(128) __half g_wq[N_DIM * K_DIM];   // 128 MiB ternary W (fp16)
__device__ __align__(128) __half g_xh[M_DIM * K_DIM];   //  64 MiB scaled X (fp16)
__device__ float g_xscale[M_DIM];
__device__ float g_partial[2048];
__device__ float g_wscale;

// ----------------------------------------------------------------------------
// Helpers
// ----------------------------------------------------------------------------
__device__ __forceinline__ uint32_t smem_u32(const void* p) {
    uint32_t a;
    asm("{ .reg .u64 t; cvta.to.shared.u64 t, %1; cvt.u32.u64 %0, t; }"
        : "=r"(a) : "l"(p));
    return a;
}

__device__ __forceinline__ uint32_t sw128(uint32_t off) {
    return off ^ ((off >> 3) & 0x70);
}

__device__ __forceinline__ void cp_async16(uint32_t dst, const void* src) {
    asm volatile("cp.async.cg.shared.global [%0], [%1], 16;"
                 :: "r"(dst), "l"(src) : "memory");
}

__device__ __forceinline__ void ldsm4(uint32_t* r, uint32_t addr) {
    asm volatile("ldmatrix.sync.aligned.m8n8.x4.shared.b16 {%0,%1,%2,%3}, [%4];"
                 : "=r"(r[0]), "=r"(r[1]), "=r"(r[2]), "=r"(r[3])
                 : "r"(addr));
}

__device__ __forceinline__ void mma16816(float* c, const uint32_t* a,
                                         uint32_t b0, uint32_t b1) {
    asm volatile(
        "mma.sync.aligned.m16n8k16.row.col.f32.f16.f16.f32 "
        "{%0,%1,%2,%3}, {%4,%5,%6,%7}, {%8,%9}, {%0,%1,%2,%3};"
        : "+f"(c[0]), "+f"(c[1]), "+f"(c[2]), "+f"(c[3])
        : "r"(a[0]), "r"(a[1]), "r"(a[2]), "r"(a[3]), "r"(b0), "r"(b1));
}

// ----------------------------------------------------------------------------
// Prep kernel 1: deterministic partial sums of |W|
// ----------------------------------------------------------------------------
__global__ void wsum_kernel(const float* __restrict__ w) {
    const int tid = threadIdx.x;
    float s = 0.0f;
    const int total = N_DIM * K_DIM;
    for (int i = blockIdx.x * blockDim.x + tid; i < total; i += gridDim.x * blockDim.x)
        s += fabsf(w[i]);
    __shared__ float sh[256];
    sh[tid] = s;
    __syncthreads();
    for (int o = 128; o > 0; o >>= 1) {
        if (tid < o) sh[tid] += sh[tid + o];
        __syncthreads();
    }
    if (tid == 0) g_partial[blockIdx.x] = sh[0];
}

// Prep kernel 2: finalize w_scale = max(mean|W|, 1e-5)
__global__ void wscale_kernel() {
    const int tid = threadIdx.x;
    float s = 0.0f;
    for (int i = tid; i < 2048; i += 256) s += g_partial[i];
    __shared__ float sh[256];
    sh[tid] = s;
    __syncthreads();
    for (int o = 128; o > 0; o >>= 1) {
        if (tid < o) sh[tid] += sh[tid + o];
        __syncthreads();
    }
    if (tid == 0)
        g_wscale = fmaxf(sh[0] / 67108864.0f, 1e-5f);
}

// Prep kernel 3: ternary-quantize W -> fp16 {-1, 0, 1}
__global__ void wq_kernel(const float* __restrict__ w) {
    const float ws = g_wscale;
    const float4* w4 = reinterpret_cast<const float4*>(w);
    __half2* out2 = reinterpret_cast<__half2*>(g_wq);
    const int total4 = (N_DIM * K_DIM) / 4;
    for (int i = blockIdx.x * blockDim.x + threadIdx.x; i < total4;
         i += gridDim.x * blockDim.x) {
        float4 v = w4[i];
        float q0 = fminf(fmaxf(rintf(v.x / ws), -1.0f), 1.0f);
        float q1 = fminf(fmaxf(rintf(v.y / ws), -1.0f), 1.0f);
        float q2 = fminf(fmaxf(rintf(v.z / ws), -1.0f), 1.0f);
        float q3 = fminf(fmaxf(rintf(v.w / ws), -1.0f), 1.0f);
        out2[2 * i + 0] = __floats2half2_rn(q0, q1);
        out2[2 * i + 1] = __floats2half2_rn(q2, q3);
    }
}

// Prep kernel 4: per-token absmax scale + fp16 scaled activations
__global__ void xprep_kernel(const float* __restrict__ x) {
    const int row = blockIdx.x;
    const int tid = threadIdx.x;
    const float4* xr = reinterpret_cast<const float4*>(x + (size_t)row * K_DIM);
    float mx = 0.0f;
    for (int i = tid; i < K_DIM / 4; i += 256) {
        float4 v = xr[i];
        mx = fmaxf(mx, fmaxf(fmaxf(fabsf(v.x), fabsf(v.y)),
                             fmaxf(fabsf(v.z), fabsf(v.w))));
    }
    __shared__ float sh[256];
    sh[tid] = mx;
    __syncthreads();
    for (int o = 128; o > 0; o >>= 1) {
        if (tid < o) sh[tid] = fmaxf(sh[tid], sh[tid + o]);
        __syncthreads();
    }
    const float xs = fmaxf(sh[0], 1e-5f);
    if (tid == 0) g_xscale[row] = xs;
    __half2* xh = reinterpret_cast<__half2*>(g_xh + (size_t)row * K_DIM);
    for (int i = tid; i < K_DIM / 4; i += 256) {
        float4 v = xr[i];
        xh[2 * i + 0] = __floats2half2_rn(v.x / xs, v.y / xs);
        xh[2 * i + 1] = __floats2half2_rn(v.z / xs, v.w / xs);
    }
}

// ----------------------------------------------------------------------------
// GEMM: out[m, n] = (sum_k xh[m,k] * wq[n,k]) * xscale[m]
// mma.sync.m16n8k16 fp16 -> fp32, 3-stage cp.async pipeline, SW128 swizzle.
// 256 threads = 8 warps (4 along M x 2 along N), warp tile 64x64.
// ----------------------------------------------------------------------------
__device__ __forceinline__ void load_stage(uint32_t s_base, int kt,
                                           const char* Ag, const char* Bg,
                                           int tid) {
    const char* a_src = Ag + (size_t)kt * (BK * 2);
    const char* b_src = Bg + (size_t)kt * (BK * 2);
#pragma unroll
    for (int i = 0; i < 8; i++) {                       // A: 256 rows x 8 chunks
        int idx = tid + i * 256;
        int r = idx >> 3, c = idx & 7;
        cp_async16(s_base + sw128((uint32_t)r * 128 + (uint32_t)c * 16),
                   a_src + (size_t)r * (K_DIM * 2) + c * 16);
    }
#pragma unroll
    for (int i = 0; i < 4; i++) {                       // B: 128 rows x 8 chunks
        int idx = tid + i * 256;
        int r = idx >> 3, c = idx & 7;
        cp_async16(s_base + A_TILE + sw128((uint32_t)r * 128 + (uint32_t)c * 16),
                   b_src + (size_t)r * (K_DIM * 2) + c * 16);
    }
    asm volatile("cp.async.commit_group;" ::: "memory");
}

__global__ void __launch_bounds__(256, 1)
bitlinear_gemm(float* __restrict__ out) {
    extern __shared__ __align__(128) char smem[];
    const uint32_t sb = smem_u32(smem);

    const int tid = threadIdx.x;
    const int lane = tid & 31;
    const int wid = tid >> 5;
    const int warp_m = wid & 3;        // 4 warps along M (64 rows each)
    const int warp_n = wid >> 2;       // 2 warps along N (64 cols each)
    const int row0 = blockIdx.x * BM;  // M fastest -> A stays L2-resident
    const int col0 = blockIdx.y * BN;

    const char* Ag = reinterpret_cast<const char*>(g_xh + (size_t)row0 * K_DIM);
    const char* Bg = reinterpret_cast<const char*>(g_wq + (size_t)col0 * K_DIM);

    float acc[4][8][4] = {};           // 4 m16-tiles x 8 n8-tiles x 4 floats

    // Prologue: fill 2 stages
    load_stage(sb + 0 * STAGE_BYTES, 0, Ag, Bg, tid);
    load_stage(sb + 1 * STAGE_BYTES, 1, Ag, Bg, tid);

    // Per-lane ldmatrix row offset: row = lane&15, col-halves = (lane>>4)*8
    const uint32_t lrow = (uint32_t)(lane & 15) * 128 + (uint32_t)(lane >> 4) * 16;

    for (int kt = 0; kt < KT; kt++) {
        if (kt < KT - 1) { asm volatile("cp.async.wait_group 1;" ::: "memory"); }
        else             { asm volatile("cp.async.wait_group 0;" ::: "memory"); }
        __syncthreads();

        // Refill the slot consumed last iteration (all warps are past it now)
        if (kt + 2 < KT)
            load_stage(sb + ((kt + 2) % STAGES) * STAGE_BYTES, kt + 2, Ag, Bg, tid);

        const uint32_t st = sb + (kt % STAGES) * STAGE_BYTES;
        const uint32_t a_base = st + (uint32_t)warp_m * 64 * 128;
        const uint32_t b_base = st + A_TILE + (uint32_t)warp_n * 64 * 128;

#pragma unroll
        for (int ks = 0; ks < BK / 16; ks++) {
            uint32_t af[4][4], bf[4][4];
#pragma unroll
            for (int mi = 0; mi < 4; mi++)
                ldsm4(af[mi], a_base + sw128(lrow + (uint32_t)mi * 2048 + (uint32_t)ks * 32));
#pragma unroll
            for (int np = 0; np < 4; np++)
                ldsm4(bf[np], b_base + sw128(lrow + (uint32_t)np * 2048 + (uint32_t)ks * 32));
#pragma unroll
            for (int mi = 0; mi < 4; mi++)
#pragma unroll
                for (int ni = 0; ni < 8; ni++)
                    mma16816(acc[mi][ni], af[mi],
                             bf[ni >> 1][ni & 1], bf[ni >> 1][(ni & 1) + 2]);
        }
    }

    // Epilogue: scale by x_scale[m] and store fp32
#pragma unroll
    for (int mi = 0; mi < 4; mi++) {
        const int m = row0 + warp_m * 64 + mi * 16 + (lane >> 2);
        const float xs0 = g_xscale[m];
        const float xs1 = g_xscale[m + 8];
        float* o0 = out + (size_t)m * N_DIM + col0 + warp_n * 64 + (lane & 3) * 2;
        float* o1 = o0 + 8 * (size_t)N_DIM;
#pragma unroll
        for (int ni = 0; ni < 8; ni++) {
            float2 v0 = make_float2(acc[mi][ni][0] * xs0, acc[mi][ni][1] * xs0);
            float2 v1 = make_float2(acc[mi][ni][2] * xs1, acc[mi][ni][3] * xs1);
            *reinterpret_cast<float2*>(o0 + ni * 8) = v0;
            *reinterpret_cast<float2*>(o1 + ni * 8) = v1;
        }
    }
}

// ----------------------------------------------------------------------------
// Launch
// ----------------------------------------------------------------------------
extern "C" void kernel_launch(void* const* d_in, const int* in_sizes, int n_in,
                              void* d_out, int out_size) {
    const float* x = (const float*)d_in[0];
    const float* w = (const float*)d_in[1];
    float* out = (float*)d_out;

    wsum_kernel<<<2048, 256>>>(w);
    wscale_kernel<<<1, 256>>>();
    wq_kernel<<<4096, 256>>>(w);
    xprep_kernel<<<M_DIM, 256>>>(x);

    cudaFuncSetAttribute(bitlinear_gemm,
                         cudaFuncAttributeMaxDynamicSharedMemorySize, SMEM_BYTES);
    dim3 grid(M_DIM / BM, N_DIM / BN);
    bitlinear_gemm<<<grid, 256, SMEM_BYTES>>>(out);
}

// round 4
// speedup vs baseline: 1.0719x; 1.0719x over previous
#include <cuda_runtime.h>
#include <cuda_fp16.h>
#include <cstdint>

// ----------------------------------------------------------------------------
// Problem sizes (fixed by the dataset)
//   x:      [2, 4096, 4096] f32  -> M = 8192 tokens, K = 4096
//   weight: [16384, 4096]   f32  -> N = 16384
//   out:    [2, 4096, 16384] f32
// ----------------------------------------------------------------------------
constexpr int M_DIM = 8192;
constexpr int N_DIM = 16384;
constexpr int K_DIM = 4096;

// GEMM tiling (mma.sync path — tcgen05 unavailable: harness targets compute_103).
// 128x128 CTA tile, 4 warps (2x2), warp tile 64x64, 3-stage cp.async.
// 96KB smem/CTA + ~185 regs/thread -> 2 CTAs co-resident per SM to overlap
// barrier/load phases of one CTA with MMA phases of the other.
constexpr int BM = 128;
constexpr int BN = 128;
constexpr int BK = 64;               // 64 fp16 = 128 B = one SW128 row
constexpr int KT = K_DIM / BK;       // 64 k-tiles
constexpr int STAGES = 3;

constexpr int A_TILE = BM * BK * 2;              // 16384 B
constexpr int B_TILE = BN * BK * 2;              // 16384 B
constexpr int STAGE_BYTES = A_TILE + B_TILE;     // 32768 B
constexpr int SMEM_BYTES = STAGES * STAGE_BYTES; // 98304 B

// ----------------------------------------------------------------------------
// Scratch (static device memory -- no allocations allowed)
// ----------------------------------------------------------------------------
__device__ __align__(128) __half g_wq[N_DIM * K_DIM];   // 128 MiB ternary W (fp16)
__device__ __align__(128) __half g_xh[M_DIM * K_DIM];   //  64 MiB scaled X (fp16)
__device__ float g_xscale[M_DIM];
__device__ float g_partial[2048];
__device__ float g_wscale;

// ----------------------------------------------------------------------------
// Helpers
// ----------------------------------------------------------------------------
__device__ __forceinline__ uint32_t smem_u32(const void* p) {
    uint32_t a;
    asm("{ .reg .u64 t; cvta.to.shared.u64 t, %1; cvt.u32.u64 %0, t; }"
        : "=r"(a) : "l"(p));
    return a;
}

__device__ __forceinline__ uint32_t sw128(uint32_t off) {
    return off ^ ((off >> 3) & 0x70);
}

__device__ __forceinline__ void cp_async16(uint32_t dst, const void* src) {
    asm volatile("cp.async.cg.shared.global [%0], [%1], 16;"
                 :: "r"(dst), "l"(src) : "memory");
}

__device__ __forceinline__ void ldsm4(uint32_t* r, uint32_t addr) {
    asm volatile("ldmatrix.sync.aligned.m8n8.x4.shared.b16 {%0,%1,%2,%3}, [%4];"
                 : "=r"(r[0]), "=r"(r[1]), "=r"(r[2]), "=r"(r[3])
                 : "r"(addr));
}

__device__ __forceinline__ void mma16816(float* c, const uint32_t* a,
                                         uint32_t b0, uint32_t b1) {
    asm volatile(
        "mma.sync.aligned.m16n8k16.row.col.f32.f16.f16.f32 "
        "{%0,%1,%2,%3}, {%4,%5,%6,%7}, {%8,%9}, {%0,%1,%2,%3};"
        : "+f"(c[0]), "+f"(c[1]), "+f"(c[2]), "+f"(c[3])
        : "r"(a[0]), "r"(a[1]), "r"(a[2]), "r"(a[3]), "r"(b0), "r"(b1));
}

// ----------------------------------------------------------------------------
// Prep kernel 1: deterministic partial sums of |W|
// ----------------------------------------------------------------------------
__global__ void wsum_kernel(const float* __restrict__ w) {
    const int tid = threadIdx.x;
    float s = 0.0f;
    const int total = N_DIM * K_DIM;
    for (int i = blockIdx.x * blockDim.x + tid; i < total; i += gridDim.x * blockDim.x)
        s += fabsf(w[i]);
    __shared__ float sh[256];
    sh[tid] = s;
    __syncthreads();
    for (int o = 128; o > 0; o >>= 1) {
        if (tid < o) sh[tid] += sh[tid + o];
        __syncthreads();
    }
    if (tid == 0) g_partial[blockIdx.x] = sh[0];
}

// Prep kernel 2: finalize w_scale = max(mean|W|, 1e-5)
__global__ void wscale_kernel() {
    const int tid = threadIdx.x;
    float s = 0.0f;
    for (int i = tid; i < 2048; i += 256) s += g_partial[i];
    __shared__ float sh[256];
    sh[tid] = s;
    __syncthreads();
    for (int o = 128; o > 0; o >>= 1) {
        if (tid < o) sh[tid] += sh[tid + o];
        __syncthreads();
    }
    if (tid == 0)
        g_wscale = fmaxf(sh[0] / 67108864.0f, 1e-5f);
}

// Prep kernel 3: ternary-quantize W -> fp16 {-1, 0, 1}
__global__ void wq_kernel(const float* __restrict__ w) {
    const float ws = g_wscale;
    const float4* w4 = reinterpret_cast<const float4*>(w);
    __half2* out2 = reinterpret_cast<__half2*>(g_wq);
    const int total4 = (N_DIM * K_DIM) / 4;
    for (int i = blockIdx.x * blockDim.x + threadIdx.x; i < total4;
         i += gridDim.x * blockDim.x) {
        float4 v = w4[i];
        float q0 = fminf(fmaxf(rintf(v.x / ws), -1.0f), 1.0f);
        float q1 = fminf(fmaxf(rintf(v.y / ws), -1.0f), 1.0f);
        float q2 = fminf(fmaxf(rintf(v.z / ws), -1.0f), 1.0f);
        float q3 = fminf(fmaxf(rintf(v.w / ws), -1.0f), 1.0f);
        out2[2 * i + 0] = __floats2half2_rn(q0, q1);
        out2[2 * i + 1] = __floats2half2_rn(q2, q3);
    }
}

// Prep kernel 4: per-token absmax scale + fp16 scaled activations
__global__ void xprep_kernel(const float* __restrict__ x) {
    const int row = blockIdx.x;
    const int tid = threadIdx.x;
    const float4* xr = reinterpret_cast<const float4*>(x + (size_t)row * K_DIM);
    float mx = 0.0f;
    for (int i = tid; i < K_DIM / 4; i += 256) {
        float4 v = xr[i];
        mx = fmaxf(mx, fmaxf(fmaxf(fabsf(v.x), fabsf(v.y)),
                             fmaxf(fabsf(v.z), fabsf(v.w))));
    }
    __shared__ float sh[256];
    sh[tid] = mx;
    __syncthreads();
    for (int o = 128; o > 0; o >>= 1) {
        if (tid < o) sh[tid] = fmaxf(sh[tid], sh[tid + o]);
        __syncthreads();
    }
    const float xs = fmaxf(sh[0], 1e-5f);
    if (tid == 0) g_xscale[row] = xs;
    __half2* xh = reinterpret_cast<__half2*>(g_xh + (size_t)row * K_DIM);
    for (int i = tid; i < K_DIM / 4; i += 256) {
        float4 v = xr[i];
        xh[2 * i + 0] = __floats2half2_rn(v.x / xs, v.y / xs);
        xh[2 * i + 1] = __floats2half2_rn(v.z / xs, v.w / xs);
    }
}

// ----------------------------------------------------------------------------
// GEMM: out[m, n] = (sum_k xh[m,k] * wq[n,k]) * xscale[m]
// mma.sync.m16n8k16 fp16 -> fp32, 3-stage cp.async pipeline, SW128 swizzle.
// 128 threads = 4 warps (2 along M x 2 along N), warp tile 64x64.
// ----------------------------------------------------------------------------
__device__ __forceinline__ void load_stage(uint32_t s_base, int kt,
                                           const char* Ag, const char* Bg,
                                           int tid) {
    const char* a_src = Ag + (size_t)kt * (BK * 2);
    const char* b_src = Bg + (size_t)kt * (BK * 2);
#pragma unroll
    for (int i = 0; i < 8; i++) {                       // A: 128 rows x 8 chunks
        int idx = tid + i * 128;
        int r = idx >> 3, c = idx & 7;
        cp_async16(s_base + sw128((uint32_t)r * 128 + (uint32_t)c * 16),
                   a_src + (size_t)r * (K_DIM * 2) + c * 16);
    }
#pragma unroll
    for (int i = 0; i < 8; i++) {                       // B: 128 rows x 8 chunks
        int idx = tid + i * 128;
        int r = idx >> 3, c = idx & 7;
        cp_async16(s_base + A_TILE + sw128((uint32_t)r * 128 + (uint32_t)c * 16),
                   b_src + (size_t)r * (K_DIM * 2) + c * 16);
    }
    asm volatile("cp.async.commit_group;" ::: "memory");
}

__global__ void __launch_bounds__(128, 2)
bitlinear_gemm(float* __restrict__ out) {
    extern __shared__ __align__(128) char smem[];
    const uint32_t sb = smem_u32(smem);

    const int tid = threadIdx.x;
    const int lane = tid & 31;
    const int wid = tid >> 5;
    const int warp_m = wid & 1;        // 2 warps along M (64 rows each)
    const int warp_n = wid >> 1;       // 2 warps along N (64 cols each)
    const int row0 = blockIdx.x * BM;  // M fastest -> A stays L2-resident
    const int col0 = blockIdx.y * BN;

    const char* Ag = reinterpret_cast<const char*>(g_xh + (size_t)row0 * K_DIM);
    const char* Bg = reinterpret_cast<const char*>(g_wq + (size_t)col0 * K_DIM);

    float acc[4][8][4] = {};           // 4 m16-tiles x 8 n8-tiles x 4 floats

    // Prologue: fill 2 stages
    load_stage(sb + 0 * STAGE_BYTES, 0, Ag, Bg, tid);
    load_stage(sb + 1 * STAGE_BYTES, 1, Ag, Bg, tid);

    // Per-lane ldmatrix row offset: row = lane&15, col-halves = (lane>>4)*8
    const uint32_t lrow = (uint32_t)(lane & 15) * 128 + (uint32_t)(lane >> 4) * 16;

    for (int kt = 0; kt < KT; kt++) {
        if (kt < KT - 1) { asm volatile("cp.async.wait_group 1;" ::: "memory"); }
        else             { asm volatile("cp.async.wait_group 0;" ::: "memory"); }
        __syncthreads();

        // Refill the slot consumed last iteration (all warps are past it now)
        if (kt + 2 < KT)
            load_stage(sb + ((kt + 2) % STAGES) * STAGE_BYTES, kt + 2, Ag, Bg, tid);

        const uint32_t st = sb + (kt % STAGES) * STAGE_BYTES;
        const uint32_t a_base = st + (uint32_t)warp_m * 64 * 128;
        const uint32_t b_base = st + A_TILE + (uint32_t)warp_n * 64 * 128;

#pragma unroll
        for (int ks = 0; ks < BK / 16; ks++) {
            uint32_t af[4][4], bf[4][4];
#pragma unroll
            for (int mi = 0; mi < 4; mi++)
                ldsm4(af[mi], a_base + sw128(lrow + (uint32_t)mi * 2048 + (uint32_t)ks * 32));
#pragma unroll
            for (int np = 0; np < 4; np++)
                ldsm4(bf[np], b_base + sw128(lrow + (uint32_t)np * 2048 + (uint32_t)ks * 32));
#pragma unroll
            for (int mi = 0; mi < 4; mi++)
#pragma unroll
                for (int ni = 0; ni < 8; ni++)
                    mma16816(acc[mi][ni], af[mi],
                             bf[ni >> 1][ni & 1], bf[ni >> 1][(ni & 1) + 2]);
        }
    }

    // Epilogue: scale by x_scale[m] and store fp32
#pragma unroll
    for (int mi = 0; mi < 4; mi++) {
        const int m = row0 + warp_m * 64 + mi * 16 + (lane >> 2);
        const float xs0 = g_xscale[m];
        const float xs1 = g_xscale[m + 8];
        float* o0 = out + (size_t)m * N_DIM + col0 + warp_n * 64 + (lane & 3) * 2;
        float* o1 = o0 + 8 * (size_t)N_DIM;
#pragma unroll
        for (int ni = 0; ni < 8; ni++) {
            float2 v0 = make_float2(acc[mi][ni][0] * xs0, acc[mi][ni][1] * xs0);
            float2 v1 = make_float2(acc[mi][ni][2] * xs1, acc[mi][ni][3] * xs1);
            *reinterpret_cast<float2*>(o0 + ni * 8) = v0;
            *reinterpret_cast<float2*>(o1 + ni * 8) = v1;
        }
    }
}

// ----------------------------------------------------------------------------
// Launch
// ----------------------------------------------------------------------------
extern "C" void kernel_launch(void* const* d_in, const int* in_sizes, int n_in,
                              void* d_out, int out_size) {
    const float* x = (const float*)d_in[0];
    const float* w = (const float*)d_in[1];
    float* out = (float*)d_out;

    wsum_kernel<<<2048, 256>>>(w);
    wscale_kernel<<<1, 256>>>();
    wq_kernel<<<4096, 256>>>(w);
    xprep_kernel<<<M_DIM, 256>>>(x);

    cudaFuncSetAttribute(bitlinear_gemm,
                         cudaFuncAttributeMaxDynamicSharedMemorySize, SMEM_BYTES);
    dim3 grid(M_DIM / BM, N_DIM / BN);
    bitlinear_gemm<<<grid, 128, SMEM_BYTES>>>(out);
}

// round 5
// speedup vs baseline: 1.0763x; 1.0041x over previous
#include <cuda_runtime.h>
#include <cuda_fp16.h>
#include <cstdint>

// ----------------------------------------------------------------------------
// Problem sizes (fixed by the dataset)
//   x:      [2, 4096, 4096] f32  -> M = 8192 tokens, K = 4096
//   weight: [16384, 4096]   f32  -> N = 16384
//   out:    [2, 4096, 16384] f32
// ----------------------------------------------------------------------------
constexpr int M_DIM = 8192;
constexpr int N_DIM = 16384;
constexpr int K_DIM = 4096;

// GEMM tiling (mma.sync path — tcgen05 unavailable: harness targets compute_103).
constexpr int BM = 128;
constexpr int BN = 128;
constexpr int BK = 64;               // 64 fp16 = 128 B = one SW128 row
constexpr int KT = K_DIM / BK;       // 64 k-tiles
constexpr int STAGES = 3;

constexpr int A_TILE = BM * BK * 2;              // 16384 B
constexpr int B_TILE = BN * BK * 2;              // 16384 B
constexpr int STAGE_BYTES = A_TILE + B_TILE;     // 32768 B
constexpr int SMEM_BYTES = STAGES * STAGE_BYTES; // 98304 B

// ----------------------------------------------------------------------------
// Scratch (static device memory -- no allocations allowed)
// ----------------------------------------------------------------------------
__device__ __align__(128) __half g_wq[N_DIM * K_DIM];   // 128 MiB ternary W (fp16)
__device__ __align__(128) __half g_xh[M_DIM * K_DIM];   //  64 MiB scaled X (fp16)
__device__ float g_xscale[M_DIM];
__device__ float g_partial[2048];

// ----------------------------------------------------------------------------
// Helpers
// ----------------------------------------------------------------------------
__device__ __forceinline__ uint32_t smem_u32(const void* p) {
    uint32_t a;
    asm("{ .reg .u64 t; cvta.to.shared.u64 t, %1; cvt.u32.u64 %0, t; }"
        : "=r"(a) : "l"(p));
    return a;
}

__device__ __forceinline__ uint32_t sw128(uint32_t off) {
    return off ^ ((off >> 3) & 0x70);
}

__device__ __forceinline__ void cp_async16(uint32_t dst, const void* src) {
    asm volatile("cp.async.cg.shared.global [%0], [%1], 16;"
                 :: "r"(dst), "l"(src) : "memory");
}

__device__ __forceinline__ void ldsm4(uint32_t* r, uint32_t addr) {
    asm volatile("ldmatrix.sync.aligned.m8n8.x4.shared.b16 {%0,%1,%2,%3}, [%4];"
                 : "=r"(r[0]), "=r"(r[1]), "=r"(r[2]), "=r"(r[3])
                 : "r"(addr));
}

__device__ __forceinline__ void mma16816(float* c, const uint32_t* a,
                                         uint32_t b0, uint32_t b1) {
    asm volatile(
        "mma.sync.aligned.m16n8k16.row.col.f32.f16.f16.f32 "
        "{%0,%1,%2,%3}, {%4,%5,%6,%7}, {%8,%9}, {%0,%1,%2,%3};"
        : "+f"(c[0]), "+f"(c[1]), "+f"(c[2]), "+f"(c[3])
        : "r"(a[0]), "r"(a[1]), "r"(a[2]), "r"(a[3]), "r"(b0), "r"(b1));
}

// ----------------------------------------------------------------------------
// Kernel 1: deterministic partial sums of |W|
// ----------------------------------------------------------------------------
__global__ void wsum_kernel(const float* __restrict__ w) {
    const int tid = threadIdx.x;
    float s = 0.0f;
    const int total = N_DIM * K_DIM;
    for (int i = blockIdx.x * blockDim.x + tid; i < total; i += gridDim.x * blockDim.x)
        s += fabsf(w[i]);
    __shared__ float sh[256];
    sh[tid] = s;
    __syncthreads();
    for (int o = 128; o > 0; o >>= 1) {
        if (tid < o) sh[tid] += sh[tid + o];
        __syncthreads();
    }
    if (tid == 0) g_partial[blockIdx.x] = sh[0];
}

// ----------------------------------------------------------------------------
// Kernel 2 (fused): every block reduces g_partial -> w_scale locally, then
// blocks [0, M_DIM) do xprep rows; blocks [M_DIM, M_DIM+4096) quantize W.
// ----------------------------------------------------------------------------
constexpr int WQ_BLOCKS = 4096;
constexpr int PREP_GRID = M_DIM + WQ_BLOCKS;

__global__ void prep_kernel(const float* __restrict__ x,
                            const float* __restrict__ w) {
    const int tid = threadIdx.x;
    __shared__ float sh[256];

    {
        float s = 0.0f;
        for (int i = tid; i < 2048; i += 256) s += g_partial[i];
        sh[tid] = s;
        __syncthreads();
        for (int o = 128; o > 0; o >>= 1) {
            if (tid < o) sh[tid] += sh[tid + o];
            __syncthreads();
        }
    }
    const float ws = fmaxf(sh[0] / 67108864.0f, 1e-5f);
    __syncthreads();

    if (blockIdx.x < M_DIM) {
        // ---- xprep: per-token absmax + fp16 scaled activations ----
        const int row = blockIdx.x;
        const float4* xr = reinterpret_cast<const float4*>(x + (size_t)row * K_DIM);
        float mx = 0.0f;
        float4 v0[4];
#pragma unroll
        for (int j = 0; j < 4; j++) {
            v0[j] = xr[tid + j * 256];
            mx = fmaxf(mx, fmaxf(fmaxf(fabsf(v0[j].x), fabsf(v0[j].y)),
                                 fmaxf(fabsf(v0[j].z), fabsf(v0[j].w))));
        }
        sh[tid] = mx;
        __syncthreads();
        for (int o = 128; o > 0; o >>= 1) {
            if (tid < o) sh[tid] = fmaxf(sh[tid], sh[tid + o]);
            __syncthreads();
        }
        const float xs = fmaxf(sh[0], 1e-5f);
        if (tid == 0) g_xscale[row] = xs;
        const float inv = 1.0f / xs;
        __half2* xh = reinterpret_cast<__half2*>(g_xh + (size_t)row * K_DIM);
#pragma unroll
        for (int j = 0; j < 4; j++) {
            const int i = tid + j * 256;
            xh[2 * i + 0] = __floats2half2_rn(v0[j].x * inv, v0[j].y * inv);
            xh[2 * i + 1] = __floats2half2_rn(v0[j].z * inv, v0[j].w * inv);
        }
    } else {
        // ---- wq: ternary-quantize W -> fp16 {-1,0,1} ----
        const int blk = blockIdx.x - M_DIM;
        const float inv_ws = 1.0f / ws;
        const float4* w4 = reinterpret_cast<const float4*>(w);
        __half2* out2 = reinterpret_cast<__half2*>(g_wq);
        const int total4 = (N_DIM * K_DIM) / 4;
        for (int i = blk * 256 + tid; i < total4; i += WQ_BLOCKS * 256) {
            float4 v = w4[i];
            float q0 = fminf(fmaxf(rintf(v.x * inv_ws), -1.0f), 1.0f);
            float q1 = fminf(fmaxf(rintf(v.y * inv_ws), -1.0f), 1.0f);
            float q2 = fminf(fmaxf(rintf(v.z * inv_ws), -1.0f), 1.0f);
            float q3 = fminf(fmaxf(rintf(v.w * inv_ws), -1.0f), 1.0f);
            out2[2 * i + 0] = __floats2half2_rn(q0, q1);
            out2[2 * i + 1] = __floats2half2_rn(q2, q3);
        }
    }
}

// ----------------------------------------------------------------------------
// Kernel 3 GEMM: out[m, n] = (sum_k xh[m,k] * wq[n,k]) * xscale[m]
// ----------------------------------------------------------------------------
__device__ __forceinline__ void load_stage(uint32_t s_base, int kt,
                                           const char* Ag, const char* Bg,
                                           int tid) {
    const char* a_src = Ag + (size_t)kt * (BK * 2);
    const char* b_src = Bg + (size_t)kt * (BK * 2);
#pragma unroll
    for (int i = 0; i < 8; i++) {
        int idx = tid + i * 128;
        int r = idx >> 3, c = idx & 7;
        cp_async16(s_base + sw128((uint32_t)r * 128 + (uint32_t)c * 16),
                   a_src + (size_t)r * (K_DIM * 2) + c * 16);
    }
#pragma unroll
    for (int i = 0; i < 8; i++) {
        int idx = tid + i * 128;
        int r = idx >> 3, c = idx & 7;
        cp_async16(s_base + A_TILE + sw128((uint32_t)r * 128 + (uint32_t)c * 16),
                   b_src + (size_t)r * (K_DIM * 2) + c * 16);
    }
    asm volatile("cp.async.commit_group;" ::: "memory");
}

__global__ void __launch_bounds__(128, 2)
bitlinear_gemm(float* __restrict__ out) {
    extern __shared__ __align__(128) char smem[];
    const uint32_t sb = smem_u32(smem);

    const int tid = threadIdx.x;
    const int lane = tid & 31;
    const int wid = tid >> 5;
    const int warp_m = wid & 1;
    const int warp_n = wid >> 1;
    const int row0 = blockIdx.x * BM;  // M fastest -> A stays L2-resident
    const int col0 = blockIdx.y * BN;

    const char* Ag = reinterpret_cast<const char*>(g_xh + (size_t)row0 * K_DIM);
    const char* Bg = reinterpret_cast<const char*>(g_wq + (size_t)col0 * K_DIM);

    float acc[4][8][4] = {};

    load_stage(sb + 0 * STAGE_BYTES, 0, Ag, Bg, tid);
    load_stage(sb + 1 * STAGE_BYTES, 1, Ag, Bg, tid);

    const uint32_t lrow = (uint32_t)(lane & 15) * 128 + (uint32_t)(lane >> 4) * 16;

    uint32_t af[2][4][4], bf[2][4][4];

    for (int kt = 0; kt < KT; kt++) {
        if (kt < KT - 1) { asm volatile("cp.async.wait_group 1;" ::: "memory"); }
        else             { asm volatile("cp.async.wait_group 0;" ::: "memory"); }
        __syncthreads();

        if (kt + 2 < KT)
            load_stage(sb + ((kt + 2) % STAGES) * STAGE_BYTES, kt + 2, Ag, Bg, tid);

        const uint32_t st = sb + (kt % STAGES) * STAGE_BYTES;
        const uint32_t a_base = st + (uint32_t)warp_m * 64 * 128;
        const uint32_t b_base = st + A_TILE + (uint32_t)warp_n * 64 * 128;

#pragma unroll
        for (int mi = 0; mi < 4; mi++)
            ldsm4(af[0][mi], a_base + sw128(lrow + (uint32_t)mi * 2048));
#pragma unroll
        for (int np = 0; np < 4; np++)
            ldsm4(bf[0][np], b_base + sw128(lrow + (uint32_t)np * 2048));

#pragma unroll
        for (int ks = 0; ks < BK / 16; ks++) {
            const int cur = ks & 1, nxt = cur ^ 1;
            if (ks < BK / 16 - 1) {
#pragma unroll
                for (int mi = 0; mi < 4; mi++)
                    ldsm4(af[nxt][mi],
                          a_base + sw128(lrow + (uint32_t)mi * 2048 + (uint32_t)(ks + 1) * 32));
#pragma unroll
                for (int np = 0; np < 4; np++)
                    ldsm4(bf[nxt][np],
                          b_base + sw128(lrow + (uint32_t)np * 2048 + (uint32_t)(ks + 1) * 32));
            }
#pragma unroll
            for (int mi = 0; mi < 4; mi++)
#pragma unroll
                for (int ni = 0; ni < 8; ni++)
                    mma16816(acc[mi][ni], af[cur][mi],
                             bf[cur][ni >> 1][ni & 1], bf[cur][ni >> 1][(ni & 1) + 2]);
        }
    }

#pragma unroll
    for (int mi = 0; mi < 4; mi++) {
        const int m = row0 + warp_m * 64 + mi * 16 + (lane >> 2);
        const float xs0 = g_xscale[m];
        const float xs1 = g_xscale[m + 8];
        float* o0 = out + (size_t)m * N_DIM + col0 + warp_n * 64 + (lane & 3) * 2;
        float* o1 = o0 + 8 * (size_t)N_DIM;
#pragma unroll
        for (int ni = 0; ni < 8; ni++) {
            float2 v0 = make_float2(acc[mi][ni][0] * xs0, acc[mi][ni][1] * xs0);
            float2 v1 = make_float2(acc[mi][ni][2] * xs1, acc[mi][ni][3] * xs1);
            *reinterpret_cast<float2*>(o0 + ni * 8) = v0;
            *reinterpret_cast<float2*>(o1 + ni * 8) = v1;
        }
    }
}

// ----------------------------------------------------------------------------
// Launch (3 kernels per call so ncu -s 5 lands on a GEMM replay)
// ----------------------------------------------------------------------------
extern "C" void kernel_launch(void* const* d_in, const int* in_sizes, int n_in,
                              void* d_out, int out_size) {
    const float* x = (const float*)d_in[0];
    const float* w = (const float*)d_in[1];
    float* out = (float*)d_out;

    wsum_kernel<<<2048, 256>>>(w);
    prep_kernel<<<PREP_GRID, 256>>>(x, w);

    cudaFuncSetAttribute(bitlinear_gemm,
                         cudaFuncAttributeMaxDynamicSharedMemorySize, SMEM_BYTES);
    dim3 grid(M_DIM / BM, N_DIM / BN);
    bitlinear_gemm<<<grid, 128, SMEM_BYTES>>>(out);
}

// round 6
// speedup vs baseline: 1.3674x; 1.2705x over previous
#include <cuda_runtime.h>
#include <cuda_fp16.h>
#include <cstdint>

// ----------------------------------------------------------------------------
// Problem sizes (fixed by the dataset)
//   x:      [2, 4096, 4096] f32  -> M = 8192 tokens, K = 4096
//   weight: [16384, 4096]   f32  -> N = 16384
//   out:    [2, 4096, 16384] f32
// ----------------------------------------------------------------------------
constexpr int M_DIM = 8192;
constexpr int N_DIM = 16384;
constexpr int K_DIM = 4096;

// GEMM tiling (mma.sync path — tcgen05 unavailable: harness targets compute_103).
constexpr int BM = 128;
constexpr int BN = 128;
constexpr int BK = 64;               // 64 fp16 = 128 B = one SW128 row
constexpr int KT = K_DIM / BK;       // 64 k-tiles
constexpr int STAGES = 3;

constexpr int A_TILE = BM * BK * 2;              // 16384 B
constexpr int B_TILE = BN * BK * 2;              // 16384 B
constexpr int STAGE_BYTES = A_TILE + B_TILE;     // 32768 B
constexpr int SMEM_BYTES = STAGES * STAGE_BYTES; // 98304 B

// ----------------------------------------------------------------------------
// Scratch (static device memory -- no allocations allowed)
// ----------------------------------------------------------------------------
__device__ __align__(128) __half g_wq[N_DIM * K_DIM];   // 128 MiB ternary W (fp16)
__device__ __align__(128) __half g_xh[M_DIM * K_DIM];   //  64 MiB scaled X (fp16)
__device__ float g_xscale[M_DIM];
__device__ float g_partial[2048];

// ----------------------------------------------------------------------------
// Helpers
// ----------------------------------------------------------------------------
__device__ __forceinline__ uint32_t smem_u32(const void* p) {
    uint32_t a;
    asm("{ .reg .u64 t; cvta.to.shared.u64 t, %1; cvt.u32.u64 %0, t; }"
        : "=r"(a) : "l"(p));
    return a;
}

__device__ __forceinline__ uint32_t sw128(uint32_t off) {
    return off ^ ((off >> 3) & 0x70);
}

__device__ __forceinline__ void cp_async16(uint32_t dst, const void* src) {
    asm volatile("cp.async.cg.shared.global [%0], [%1], 16;"
                 :: "r"(dst), "l"(src) : "memory");
}

__device__ __forceinline__ void ldsm4(uint32_t* r, uint32_t addr) {
    asm volatile("ldmatrix.sync.aligned.m8n8.x4.shared.b16 {%0,%1,%2,%3}, [%4];"
                 : "=r"(r[0]), "=r"(r[1]), "=r"(r[2]), "=r"(r[3])
                 : "r"(addr));
}

__device__ __forceinline__ void mma16816(float* c, const uint32_t* a,
                                         uint32_t b0, uint32_t b1) {
    asm volatile(
        "mma.sync.aligned.m16n8k16.row.col.f32.f16.f16.f32 "
        "{%0,%1,%2,%3}, {%4,%5,%6,%7}, {%8,%9}, {%0,%1,%2,%3};"
        : "+f"(c[0]), "+f"(c[1]), "+f"(c[2]), "+f"(c[3])
        : "r"(a[0]), "r"(a[1]), "r"(a[2]), "r"(a[3]), "r"(b0), "r"(b1));
}

// ----------------------------------------------------------------------------
// Kernel 1: deterministic partial sums of |W| (vectorized float4, 4 chains)
// ----------------------------------------------------------------------------
__global__ void wsum_kernel(const float* __restrict__ w) {
    const int tid = threadIdx.x;
    const float4* w4 = reinterpret_cast<const float4*>(w);
    const int total4 = (N_DIM * K_DIM) / 4;           // 16777216
    float s0 = 0.f, s1 = 0.f, s2 = 0.f, s3 = 0.f;
    for (int i = blockIdx.x * blockDim.x + tid; i < total4;
         i += gridDim.x * blockDim.x) {
        float4 v = w4[i];
        s0 += fabsf(v.x); s1 += fabsf(v.y);
        s2 += fabsf(v.z); s3 += fabsf(v.w);
    }
    __shared__ float sh[256];
    sh[tid] = (s0 + s1) + (s2 + s3);
    __syncthreads();
    for (int o = 128; o > 0; o >>= 1) {
        if (tid < o) sh[tid] += sh[tid + o];
        __syncthreads();
    }
    if (tid == 0) g_partial[blockIdx.x] = sh[0];
}

// ----------------------------------------------------------------------------
// Kernel 2 (fused): every block reduces g_partial -> w_scale locally, then
// blocks [0, M_DIM) do xprep rows; blocks [M_DIM, M_DIM+4096) quantize W.
// ----------------------------------------------------------------------------
constexpr int WQ_BLOCKS = 4096;
constexpr int PREP_GRID = M_DIM + WQ_BLOCKS;

__global__ void prep_kernel(const float* __restrict__ x,
                            const float* __restrict__ w) {
    const int tid = threadIdx.x;
    __shared__ float sh[256];

    {
        float s = 0.0f;
        for (int i = tid; i < 2048; i += 256) s += g_partial[i];
        sh[tid] = s;
        __syncthreads();
        for (int o = 128; o > 0; o >>= 1) {
            if (tid < o) sh[tid] += sh[tid + o];
            __syncthreads();
        }
    }
    const float ws = fmaxf(sh[0] / 67108864.0f, 1e-5f);
    __syncthreads();

    if (blockIdx.x < M_DIM) {
        // ---- xprep: per-token absmax + fp16 scaled activations ----
        const int row = blockIdx.x;
        const float4* xr = reinterpret_cast<const float4*>(x + (size_t)row * K_DIM);
        float mx = 0.0f;
        float4 v0[4];
#pragma unroll
        for (int j = 0; j < 4; j++) {
            v0[j] = xr[tid + j * 256];
            mx = fmaxf(mx, fmaxf(fmaxf(fabsf(v0[j].x), fabsf(v0[j].y)),
                                 fmaxf(fabsf(v0[j].z), fabsf(v0[j].w))));
        }
        sh[tid] = mx;
        __syncthreads();
        for (int o = 128; o > 0; o >>= 1) {
            if (tid < o) sh[tid] = fmaxf(sh[tid], sh[tid + o]);
            __syncthreads();
        }
        const float xs = fmaxf(sh[0], 1e-5f);
        if (tid == 0) g_xscale[row] = xs;
        const float inv = 1.0f / xs;
        __half2* xh = reinterpret_cast<__half2*>(g_xh + (size_t)row * K_DIM);
#pragma unroll
        for (int j = 0; j < 4; j++) {
            const int i = tid + j * 256;
            xh[2 * i + 0] = __floats2half2_rn(v0[j].x * inv, v0[j].y * inv);
            xh[2 * i + 1] = __floats2half2_rn(v0[j].z * inv, v0[j].w * inv);
        }
    } else {
        // ---- wq: ternary-quantize W -> fp16 {-1,0,1} ----
        const int blk = blockIdx.x - M_DIM;
        const float inv_ws = 1.0f / ws;
        const float4* w4 = reinterpret_cast<const float4*>(w);
        __half2* out2 = reinterpret_cast<__half2*>(g_wq);
        const int total4 = (N_DIM * K_DIM) / 4;
        for (int i = blk * 256 + tid; i < total4; i += WQ_BLOCKS * 256) {
            float4 v = w4[i];
            float q0 = fminf(fmaxf(rintf(v.x * inv_ws), -1.0f), 1.0f);
            float q1 = fminf(fmaxf(rintf(v.y * inv_ws), -1.0f), 1.0f);
            float q2 = fminf(fmaxf(rintf(v.z * inv_ws), -1.0f), 1.0f);
            float q3 = fminf(fmaxf(rintf(v.w * inv_ws), -1.0f), 1.0f);
            out2[2 * i + 0] = __floats2half2_rn(q0, q1);
            out2[2 * i + 1] = __floats2half2_rn(q2, q3);
        }
    }
}

// ----------------------------------------------------------------------------
// Kernel 3 GEMM: out[m, n] = (sum_k xh[m,k] * wq[n,k]) * xscale[m]
// mma.sync fp16->fp32, 3-stage cp.async, SW128, 4 warps (2x2), 2 CTAs/SM.
// Cross-tile fragment pipelining: the barrier lives at the END of each tile's
// MMA phase; next tile's ks=0 fragments prefetch right after, so every tile
// opens with MMAs instead of an LDSM-latency bubble.
// ----------------------------------------------------------------------------
__device__ __forceinline__ void load_stage(uint32_t s_base, int kt,
                                           const char* Ag, const char* Bg,
                                           int tid) {
    const char* a_src = Ag + (size_t)kt * (BK * 2);
    const char* b_src = Bg + (size_t)kt * (BK * 2);
#pragma unroll
    for (int i = 0; i < 8; i++) {
        int idx = tid + i * 128;
        int r = idx >> 3, c = idx & 7;
        cp_async16(s_base + sw128((uint32_t)r * 128 + (uint32_t)c * 16),
                   a_src + (size_t)r * (K_DIM * 2) + c * 16);
    }
#pragma unroll
    for (int i = 0; i < 8; i++) {
        int idx = tid + i * 128;
        int r = idx >> 3, c = idx & 7;
        cp_async16(s_base + A_TILE + sw128((uint32_t)r * 128 + (uint32_t)c * 16),
                   b_src + (size_t)r * (K_DIM * 2) + c * 16);
    }
    asm volatile("cp.async.commit_group;" ::: "memory");
}

__global__ void __launch_bounds__(128, 2)
bitlinear_gemm(float* __restrict__ out) {
    extern __shared__ __align__(128) char smem[];
    const uint32_t sb = smem_u32(smem);

    const int tid = threadIdx.x;
    const int lane = tid & 31;
    const int wid = tid >> 5;
    const int warp_m = wid & 1;
    const int warp_n = wid >> 1;
    const int row0 = blockIdx.x * BM;  // M fastest -> A stays L2-resident
    const int col0 = blockIdx.y * BN;

    const char* Ag = reinterpret_cast<const char*>(g_xh + (size_t)row0 * K_DIM);
    const char* Bg = reinterpret_cast<const char*>(g_wq + (size_t)col0 * K_DIM);

    float acc[4][8][4] = {};

    // Prologue: fill stages 0,1; make stage 0 visible; prefetch (kt=0, ks=0)
    load_stage(sb + 0 * STAGE_BYTES, 0, Ag, Bg, tid);
    load_stage(sb + 1 * STAGE_BYTES, 1, Ag, Bg, tid);
    asm volatile("cp.async.wait_group 1;" ::: "memory");
    __syncthreads();

    const uint32_t lrow = (uint32_t)(lane & 15) * 128 + (uint32_t)(lane >> 4) * 16;
    const uint32_t a_off = (uint32_t)warp_m * 64 * 128;
    const uint32_t b_off = A_TILE + (uint32_t)warp_n * 64 * 128;

    uint32_t af[2][4][4], bf[2][4][4];
    {
        const uint32_t st = sb;  // stage 0
#pragma unroll
        for (int mi = 0; mi < 4; mi++)
            ldsm4(af[0][mi], st + a_off + sw128(lrow + (uint32_t)mi * 2048));
#pragma unroll
        for (int np = 0; np < 4; np++)
            ldsm4(bf[0][np], st + b_off + sw128(lrow + (uint32_t)np * 2048));
    }

    for (int kt = 0; kt < KT; kt++) {
        const uint32_t st = sb + (kt % STAGES) * STAGE_BYTES;

        // Refill the stage consumed last iteration (end-of-prev-iter barrier
        // guarantees all warps finished reading it).
        if (kt + 2 < KT)
            load_stage(sb + ((kt + 2) % STAGES) * STAGE_BYTES, kt + 2, Ag, Bg, tid);

#pragma unroll
        for (int ks = 0; ks < BK / 16; ks++) {
            const int cur = ks & 1, nxt = cur ^ 1;
            if (ks < BK / 16 - 1) {
#pragma unroll
                for (int mi = 0; mi < 4; mi++)
                    ldsm4(af[nxt][mi],
                          st + a_off + sw128(lrow + (uint32_t)mi * 2048 + (uint32_t)(ks + 1) * 32));
#pragma unroll
                for (int np = 0; np < 4; np++)
                    ldsm4(bf[nxt][np],
                          st + b_off + sw128(lrow + (uint32_t)np * 2048 + (uint32_t)(ks + 1) * 32));
            }
#pragma unroll
            for (int mi = 0; mi < 4; mi++)
#pragma unroll
                for (int ni = 0; ni < 8; ni++)
                    mma16816(acc[mi][ni], af[cur][mi],
                             bf[cur][ni >> 1][ni & 1], bf[cur][ni >> 1][(ni & 1) + 2]);
        }

        // End-of-tile: ensure next stage's data is complete and visible, then
        // prefetch (kt+1, ks=0) fragments so the next tile opens with MMAs.
        if (kt + 1 < KT) {
            if (kt + 2 < KT) { asm volatile("cp.async.wait_group 1;" ::: "memory"); }
            else             { asm volatile("cp.async.wait_group 0;" ::: "memory"); }
            __syncthreads();
            const uint32_t stn = sb + ((kt + 1) % STAGES) * STAGE_BYTES;
#pragma unroll
            for (int mi = 0; mi < 4; mi++)
                ldsm4(af[0][mi], stn + a_off + sw128(lrow + (uint32_t)mi * 2048));
#pragma unroll
            for (int np = 0; np < 4; np++)
                ldsm4(bf[0][np], stn + b_off + sw128(lrow + (uint32_t)np * 2048));
        }
    }

    // Epilogue: scale by x_scale[m] and store fp32
#pragma unroll
    for (int mi = 0; mi < 4; mi++) {
        const int m = row0 + warp_m * 64 + mi * 16 + (lane >> 2);
        const float xs0 = g_xscale[m];
        const float xs1 = g_xscale[m + 8];
        float* o0 = out + (size_t)m * N_DIM + col0 + warp_n * 64 + (lane & 3) * 2;
        float* o1 = o0 + 8 * (size_t)N_DIM;
#pragma unroll
        for (int ni = 0; ni < 8; ni++) {
            float2 v0 = make_float2(acc[mi][ni][0] * xs0, acc[mi][ni][1] * xs0);
            float2 v1 = make_float2(acc[mi][ni][2] * xs1, acc[mi][ni][3] * xs1);
            *reinterpret_cast<float2*>(o0 + ni * 8) = v0;
            *reinterpret_cast<float2*>(o1 + ni * 8) = v1;
        }
    }
}

// ----------------------------------------------------------------------------
// Launch
// ----------------------------------------------------------------------------
extern "C" void kernel_launch(void* const* d_in, const int* in_sizes, int n_in,
                              void* d_out, int out_size) {
    const float* x = (const float*)d_in[0];
    const float* w = (const float*)d_in[1];
    float* out = (float*)d_out;

    wsum_kernel<<<2048, 256>>>(w);
    prep_kernel<<<PREP_GRID, 256>>>(x, w);

    cudaFuncSetAttribute(bitlinear_gemm,
                         cudaFuncAttributeMaxDynamicSharedMemorySize, SMEM_BYTES);
    dim3 grid(M_DIM / BM, N_DIM / BN);
    bitlinear_gemm<<<grid, 128, SMEM_BYTES>>>(out);
}

// round 7
// speedup vs baseline: 1.3705x; 1.0022x over previous
#include <cuda_runtime.h>
#include <cuda_fp16.h>
#include <cstdint>

// ----------------------------------------------------------------------------
// Problem sizes (fixed by the dataset)
//   x:      [2, 4096, 4096] f32  -> M = 8192 tokens, K = 4096
//   weight: [16384, 4096]   f32  -> N = 16384
//   out:    [2, 4096, 16384] f32
// ----------------------------------------------------------------------------
constexpr int M_DIM = 8192;
constexpr int N_DIM = 16384;
constexpr int K_DIM = 4096;

// GEMM tiling (mma.sync path — tcgen05 unavailable: harness targets compute_103).
constexpr int BM = 128;
constexpr int BN = 128;
constexpr int BK = 64;               // 64 fp16 = 128 B = one SW128 row
constexpr int KT = K_DIM / BK;       // 64 k-tiles
constexpr int STAGES = 3;

constexpr int A_TILE = BM * BK * 2;              // 16384 B
constexpr int B_TILE = BN * BK * 2;              // 16384 B
constexpr int STAGE_BYTES = A_TILE + B_TILE;     // 32768 B
constexpr int SMEM_BYTES = STAGES * STAGE_BYTES; // 98304 B

// ----------------------------------------------------------------------------
// Scratch (static device memory -- no allocations allowed)
// ----------------------------------------------------------------------------
__device__ __align__(128) __half g_wq[N_DIM * K_DIM];   // 128 MiB ternary W (fp16)
__device__ __align__(128) __half g_xh[M_DIM * K_DIM];   //  64 MiB scaled X (fp16)
__device__ float g_xscale[M_DIM];
__device__ float g_partial[2048];

// ----------------------------------------------------------------------------
// Helpers
// ----------------------------------------------------------------------------
__device__ __forceinline__ uint32_t smem_u32(const void* p) {
    uint32_t a;
    asm("{ .reg .u64 t; cvta.to.shared.u64 t, %1; cvt.u32.u64 %0, t; }"
        : "=r"(a) : "l"(p));
    return a;
}

__device__ __forceinline__ uint32_t sw128(uint32_t off) {
    return off ^ ((off >> 3) & 0x70);
}

__device__ __forceinline__ void cp_async16(uint32_t dst, const void* src) {
    asm volatile("cp.async.cg.shared.global [%0], [%1], 16;"
                 :: "r"(dst), "l"(src) : "memory");
}

__device__ __forceinline__ void ldsm4(uint32_t* r, uint32_t addr) {
    asm volatile("ldmatrix.sync.aligned.m8n8.x4.shared.b16 {%0,%1,%2,%3}, [%4];"
                 : "=r"(r[0]), "=r"(r[1]), "=r"(r[2]), "=r"(r[3])
                 : "r"(addr));
}

__device__ __forceinline__ void mma16816(float* c, const uint32_t* a,
                                         uint32_t b0, uint32_t b1) {
    asm volatile(
        "mma.sync.aligned.m16n8k16.row.col.f32.f16.f16.f32 "
        "{%0,%1,%2,%3}, {%4,%5,%6,%7}, {%8,%9}, {%0,%1,%2,%3};"
        : "+f"(c[0]), "+f"(c[1]), "+f"(c[2]), "+f"(c[3])
        : "r"(a[0]), "r"(a[1]), "r"(a[2]), "r"(a[3]), "r"(b0), "r"(b1));
}

// ----------------------------------------------------------------------------
// Kernel 1: deterministic partial sums of |W| (vectorized float4, 4 chains)
// ----------------------------------------------------------------------------
__global__ void wsum_kernel(const float* __restrict__ w) {
    const int tid = threadIdx.x;
    const float4* w4 = reinterpret_cast<const float4*>(w);
    const int total4 = (N_DIM * K_DIM) / 4;           // 16777216
    float s0 = 0.f, s1 = 0.f, s2 = 0.f, s3 = 0.f;
    for (int i = blockIdx.x * blockDim.x + tid; i < total4;
         i += gridDim.x * blockDim.x) {
        float4 v = w4[i];
        s0 += fabsf(v.x); s1 += fabsf(v.y);
        s2 += fabsf(v.z); s3 += fabsf(v.w);
    }
    __shared__ float sh[256];
    sh[tid] = (s0 + s1) + (s2 + s3);
    __syncthreads();
    for (int o = 128; o > 0; o >>= 1) {
        if (tid < o) sh[tid] += sh[tid + o];
        __syncthreads();
    }
    if (tid == 0) g_partial[blockIdx.x] = sh[0];
}

// ----------------------------------------------------------------------------
// Kernel 2 (fused): every block reduces g_partial -> w_scale locally, then
// blocks [0, M_DIM) do xprep rows; blocks [M_DIM, M_DIM+4096) quantize W.
// ----------------------------------------------------------------------------
constexpr int WQ_BLOCKS = 4096;
constexpr int PREP_GRID = M_DIM + WQ_BLOCKS;

__global__ void prep_kernel(const float* __restrict__ x,
                            const float* __restrict__ w) {
    const int tid = threadIdx.x;
    __shared__ float sh[256];

    {
        float s = 0.0f;
        for (int i = tid; i < 2048; i += 256) s += g_partial[i];
        sh[tid] = s;
        __syncthreads();
        for (int o = 128; o > 0; o >>= 1) {
            if (tid < o) sh[tid] += sh[tid + o];
            __syncthreads();
        }
    }
    const float ws = fmaxf(sh[0] / 67108864.0f, 1e-5f);
    __syncthreads();

    if (blockIdx.x < M_DIM) {
        // ---- xprep: per-token absmax + fp16 scaled activations ----
        const int row = blockIdx.x;
        const float4* xr = reinterpret_cast<const float4*>(x + (size_t)row * K_DIM);
        float mx = 0.0f;
        float4 v0[4];
#pragma unroll
        for (int j = 0; j < 4; j++) {
            v0[j] = xr[tid + j * 256];
            mx = fmaxf(mx, fmaxf(fmaxf(fabsf(v0[j].x), fabsf(v0[j].y)),
                                 fmaxf(fabsf(v0[j].z), fabsf(v0[j].w))));
        }
        sh[tid] = mx;
        __syncthreads();
        for (int o = 128; o > 0; o >>= 1) {
            if (tid < o) sh[tid] = fmaxf(sh[tid], sh[tid + o]);
            __syncthreads();
        }
        const float xs = fmaxf(sh[0], 1e-5f);
        if (tid == 0) g_xscale[row] = xs;
        const float inv = 1.0f / xs;
        __half2* xh = reinterpret_cast<__half2*>(g_xh + (size_t)row * K_DIM);
#pragma unroll
        for (int j = 0; j < 4; j++) {
            const int i = tid + j * 256;
            xh[2 * i + 0] = __floats2half2_rn(v0[j].x * inv, v0[j].y * inv);
            xh[2 * i + 1] = __floats2half2_rn(v0[j].z * inv, v0[j].w * inv);
        }
    } else {
        // ---- wq: ternary-quantize W -> fp16 {-1,0,1} ----
        const int blk = blockIdx.x - M_DIM;
        const float inv_ws = 1.0f / ws;
        const float4* w4 = reinterpret_cast<const float4*>(w);
        __half2* out2 = reinterpret_cast<__half2*>(g_wq);
        const int total4 = (N_DIM * K_DIM) / 4;
        for (int i = blk * 256 + tid; i < total4; i += WQ_BLOCKS * 256) {
            float4 v = w4[i];
            float q0 = fminf(fmaxf(rintf(v.x * inv_ws), -1.0f), 1.0f);
            float q1 = fminf(fmaxf(rintf(v.y * inv_ws), -1.0f), 1.0f);
            float q2 = fminf(fmaxf(rintf(v.z * inv_ws), -1.0f), 1.0f);
            float q3 = fminf(fmaxf(rintf(v.w * inv_ws), -1.0f), 1.0f);
            out2[2 * i + 0] = __floats2half2_rn(q0, q1);
            out2[2 * i + 1] = __floats2half2_rn(q2, q3);
        }
    }
}

// ----------------------------------------------------------------------------
// Kernel 3 GEMM: out[m, n] = (sum_k xh[m,k] * wq[n,k]) * xscale[m]
// mma.sync fp16->fp32, 3-stage cp.async, SW128, 4 warps (2x2), 2 CTAs/SM.
// Cross-tile fragment pipelining: the barrier lives at the END of each tile's
// MMA phase; next tile's ks=0 fragments prefetch right after, so every tile
// opens with MMAs instead of an LDSM-latency bubble.
// ----------------------------------------------------------------------------
__device__ __forceinline__ void load_stage(uint32_t s_base, int kt,
                                           const char* Ag, const char* Bg,
                                           int tid) {
    const char* a_src = Ag + (size_t)kt * (BK * 2);
    const char* b_src = Bg + (size_t)kt * (BK * 2);
#pragma unroll
    for (int i = 0; i < 8; i++) {
        int idx = tid + i * 128;
        int r = idx >> 3, c = idx & 7;
        cp_async16(s_base + sw128((uint32_t)r * 128 + (uint32_t)c * 16),
                   a_src + (size_t)r * (K_DIM * 2) + c * 16);
    }
#pragma unroll
    for (int i = 0; i < 8; i++) {
        int idx = tid + i * 128;
        int r = idx >> 3, c = idx & 7;
        cp_async16(s_base + A_TILE + sw128((uint32_t)r * 128 + (uint32_t)c * 16),
                   b_src + (size_t)r * (K_DIM * 2) + c * 16);
    }
    asm volatile("cp.async.commit_group;" ::: "memory");
}

__global__ void __launch_bounds__(128, 2)
bitlinear_gemm(float* __restrict__ out) {
    extern __shared__ __align__(128) char smem[];
    const uint32_t sb = smem_u32(smem);

    const int tid = threadIdx.x;
    const int lane = tid & 31;
    const int wid = tid >> 5;
    const int warp_m = wid & 1;
    const int warp_n = wid >> 1;
    const int row0 = blockIdx.x * BM;  // M fastest -> A stays L2-resident
    const int col0 = blockIdx.y * BN;

    const char* Ag = reinterpret_cast<const char*>(g_xh + (size_t)row0 * K_DIM);
    const char* Bg = reinterpret_cast<const char*>(g_wq + (size_t)col0 * K_DIM);

    float acc[4][8][4] = {};

    // Prologue: fill stages 0,1; make stage 0 visible; prefetch (kt=0, ks=0)
    load_stage(sb + 0 * STAGE_BYTES, 0, Ag, Bg, tid);
    load_stage(sb + 1 * STAGE_BYTES, 1, Ag, Bg, tid);
    asm volatile("cp.async.wait_group 1;" ::: "memory");
    __syncthreads();

    const uint32_t lrow = (uint32_t)(lane & 15) * 128 + (uint32_t)(lane >> 4) * 16;
    const uint32_t a_off = (uint32_t)warp_m * 64 * 128;
    const uint32_t b_off = A_TILE + (uint32_t)warp_n * 64 * 128;

    uint32_t af[2][4][4], bf[2][4][4];
    {
        const uint32_t st = sb;  // stage 0
#pragma unroll
        for (int mi = 0; mi < 4; mi++)
            ldsm4(af[0][mi], st + a_off + sw128(lrow + (uint32_t)mi * 2048));
#pragma unroll
        for (int np = 0; np < 4; np++)
            ldsm4(bf[0][np], st + b_off + sw128(lrow + (uint32_t)np * 2048));
    }

    for (int kt = 0; kt < KT; kt++) {
        const uint32_t st = sb + (kt % STAGES) * STAGE_BYTES;

        // Refill the stage consumed last iteration (end-of-prev-iter barrier
        // guarantees all warps finished reading it).
        if (kt + 2 < KT)
            load_stage(sb + ((kt + 2) % STAGES) * STAGE_BYTES, kt + 2, Ag, Bg, tid);

#pragma unroll
        for (int ks = 0; ks < BK / 16; ks++) {
            const int cur = ks & 1, nxt = cur ^ 1;
            if (ks < BK / 16 - 1) {
#pragma unroll
                for (int mi = 0; mi < 4; mi++)
                    ldsm4(af[nxt][mi],
                          st + a_off + sw128(lrow + (uint32_t)mi * 2048 + (uint32_t)(ks + 1) * 32));
#pragma unroll
                for (int np = 0; np < 4; np++)
                    ldsm4(bf[nxt][np],
                          st + b_off + sw128(lrow + (uint32_t)np * 2048 + (uint32_t)(ks + 1) * 32));
            }
#pragma unroll
            for (int mi = 0; mi < 4; mi++)
#pragma unroll
                for (int ni = 0; ni < 8; ni++)
                    mma16816(acc[mi][ni], af[cur][mi],
                             bf[cur][ni >> 1][ni & 1], bf[cur][ni >> 1][(ni & 1) + 2]);
        }

        // End-of-tile: ensure next stage's data is complete and visible, then
        // prefetch (kt+1, ks=0) fragments so the next tile opens with MMAs.
        if (kt + 1 < KT) {
            if (kt + 2 < KT) { asm volatile("cp.async.wait_group 1;" ::: "memory"); }
            else             { asm volatile("cp.async.wait_group 0;" ::: "memory"); }
            __syncthreads();
            const uint32_t stn = sb + ((kt + 1) % STAGES) * STAGE_BYTES;
#pragma unroll
            for (int mi = 0; mi < 4; mi++)
                ldsm4(af[0][mi], stn + a_off + sw128(lrow + (uint32_t)mi * 2048));
#pragma unroll
            for (int np = 0; np < 4; np++)
                ldsm4(bf[0][np], stn + b_off + sw128(lrow + (uint32_t)np * 2048));
        }
    }

    // Epilogue: scale by x_scale[m] and store fp32
#pragma unroll
    for (int mi = 0; mi < 4; mi++) {
        const int m = row0 + warp_m * 64 + mi * 16 + (lane >> 2);
        const float xs0 = g_xscale[m];
        const float xs1 = g_xscale[m + 8];
        float* o0 = out + (size_t)m * N_DIM + col0 + warp_n * 64 + (lane & 3) * 2;
        float* o1 = o0 + 8 * (size_t)N_DIM;
#pragma unroll
        for (int ni = 0; ni < 8; ni++) {
            float2 v0 = make_float2(acc[mi][ni][0] * xs0, acc[mi][ni][1] * xs0);
            float2 v1 = make_float2(acc[mi][ni][2] * xs1, acc[mi][ni][3] * xs1);
            *reinterpret_cast<float2*>(o0 + ni * 8) = v0;
            *reinterpret_cast<float2*>(o1 + ni * 8) = v1;
        }
    }
}

// ----------------------------------------------------------------------------
// Launch
// ----------------------------------------------------------------------------
extern "C" void kernel_launch(void* const* d_in, const int* in_sizes, int n_in,
                              void* d_out, int out_size) {
    const float* x = (const float*)d_in[0];
    const float* w = (const float*)d_in[1];
    float* out = (float*)d_out;

    wsum_kernel<<<2048, 256>>>(w);
    prep_kernel<<<PREP_GRID, 256>>>(x, w);

    cudaFuncSetAttribute(bitlinear_gemm,
                         cudaFuncAttributeMaxDynamicSharedMemorySize, SMEM_BYTES);
    dim3 grid(M_DIM / BM, N_DIM / BN);
    bitlinear_gemm<<<grid, 128, SMEM_BYTES>>>(out);
}